// round 3
// baseline (speedup 1.0000x reference)
#include <cuda_runtime.h>

// -----------------------------------------------------------------------------
// Round 3: tf32 mma.sync flash attention, vectorized fragment loads.
// BQ=128 x BK=64, D=64, 256 threads (8 warps, 16 q-rows each).
// K/V/P stored with column permutation pos(d) = (d&7)*8 + (d>>3), stride 68:
// all mma fragment loads become conflict-free LDS.128.
// PV computed as O^T = V^T * P^T (V stored transposed) so its operand loads
// vectorize the same way. K/V double-buffered via LDG->reg->STS.
// -----------------------------------------------------------------------------

#define NT 256
#define QKSCALE (0.125f * 1.44269504088896f)

// units sorted by descending seqlen
__constant__ int c_seqlen[8] = {1152, 1008, 864, 720, 640, 560, 480, 400};
__constant__ int c_batch[8]  = {1,    5,    3,   7,   0,   4,   2,   6};
__constant__ int c_soff[8]   = {512,  512,  512, 512, 0,   0,   0,   0};
__constant__ int c_obase[8]  = {2080, 4096, 3232, 5104, 0, 1120, 640, 1680};
__constant__ int c_qstart[8] = {0, 9, 17, 24, 30, 35, 40, 44};   // cum ceil(seq/128); total 48

#define STR 68
#define SM_QP 0                       // Q (prologue) overlaid with P (mainloop): 128 x 68
#define SM_K0 (128*STR)
#define SM_K1 (SM_K0 + 64*STR)
#define SM_V0 (SM_K1 + 64*STR)
#define SM_V1 (SM_V0 + 64*STR)
#define SM_TOTAL_FLOATS (SM_V1 + 64*STR)   // 26112 floats = 104448 B

__device__ __forceinline__ unsigned f2tf(float f) {
    unsigned u; asm("cvt.rna.tf32.f32 %0, %1;" : "=r"(u) : "f"(f)); return u;
}
__device__ __forceinline__ float ex2(float x) {
    float y; asm("ex2.approx.f32 %0, %1;" : "=f"(y) : "f"(x)); return y;
}
__device__ __forceinline__ void mma8(float d[4], const unsigned a[4], unsigned b0, unsigned b1) {
    asm volatile("mma.sync.aligned.m16n8k8.row.col.f32.tf32.tf32.f32 "
                 "{%0,%1,%2,%3}, {%4,%5,%6,%7}, {%8,%9}, {%0,%1,%2,%3};"
                 : "+f"(d[0]), "+f"(d[1]), "+f"(d[2]), "+f"(d[3])
                 : "r"(a[0]), "r"(a[1]), "r"(a[2]), "r"(a[3]), "r"(b0), "r"(b1));
}
#define U(x) __float_as_uint(x)

__global__ __launch_bounds__(NT, 1) void fa_tf32v_kernel(
    const float* __restrict__ gq, const float* __restrict__ gk, const float* __restrict__ gv,
    const float* __restrict__ eq, const float* __restrict__ ek, const float* __restrict__ ev,
    float* __restrict__ gout)
{
    extern __shared__ float sm[];
    float* QP = sm + SM_QP;
    float* Kb[2] = { sm + SM_K0, sm + SM_K1 };
    float* Vb[2] = { sm + SM_V0, sm + SM_V1 };

    const int h  = blockIdx.y;
    const int bx = blockIdx.x;
    int u = 0;
    #pragma unroll
    for (int i = 1; i < 8; i++) u += (bx >= c_qstart[i]);
    const int seqlen = c_seqlen[u];
    const int q0     = (bx - c_qstart[u]) * 128;
    const int b      = c_batch[u];
    const int soff   = c_soff[u];
    const int obase  = c_obase[u];

    const int tid  = threadIdx.x;
    const int lane = tid & 31;
    const int gID  = lane >> 2;
    const int t4   = lane & 3;
    const int m0   = (tid >> 5) * 16;          // warp's local q-row base

    // loader thread mapping: row = tid>>2 (0..63), quarter qq = tid&3
    const int lr = tid >> 2;
    const int lq = tid & 3;

    // ---- prologue: Q -> QP (linear, scaled, tf32) ----
    #pragma unroll
    for (int it = 0; it < 8; it++) {
        int idx = tid + NT * it;               // 0..2047 = 128 rows x 16 float4
        int row = idx >> 4, c4 = idx & 15;
        int rg  = q0 + row;                    // < ceil128(seqlen) <= lc: valid memory
        const float* src = (rg < 128)
            ? (eq + (((b * 128  + rg            ) * 16 + h) * 64) + 4 * c4)
            : (gq + (((b * 1536 + soff + rg - 128) * 16 + h) * 64) + 4 * c4);
        float4 v = *(const float4*)src;
        uint4 o;
        o.x = f2tf(v.x * QKSCALE); o.y = f2tf(v.y * QKSCALE);
        o.z = f2tf(v.z * QKSCALE); o.w = f2tf(v.w * QKSCALE);
        *(uint4*)(QP + row * STR + 4 * c4) = o;
    }

    // ---- prologue: K/V tile 0 -> buffers 0 (LDG -> permuted STS) ----
    {
        int rg = lr;   // k0 = 0
        const float* bk = (rg < 128)
            ? (ek + ((b * 128  + rg            ) * 16 + h) * 64)
            : (gk + ((b * 1536 + soff + rg - 128) * 16 + h) * 64);
        const float* bv = (rg < 128)
            ? (ev + ((b * 128  + rg            ) * 16 + h) * 64)
            : (gv + ((b * 1536 + soff + rg - 128) * 16 + h) * 64);
        const int pcol = ((lr & 7) << 3) + (lr >> 3);
        #pragma unroll
        for (int j = 0; j < 4; j++) {
            float4 kv = *(const float4*)(bk + (lq + 4 * j) * 4);
            float4 vv = *(const float4*)(bv + (lq + 4 * j) * 4);
            int d0 = (lq + 4 * j) * 4;
            float ka[4] = {kv.x, kv.y, kv.z, kv.w};
            float va[4] = {vv.x, vv.y, vv.z, vv.w};
            #pragma unroll
            for (int i = 0; i < 4; i++) {
                int d = d0 + i;
                Kb[0][lr * STR + ((d & 7) << 3) + (d >> 3)] = __uint_as_float(f2tf(ka[i]));
                Vb[0][d * STR + pcol]                       = __uint_as_float(f2tf(va[i]));
            }
        }
    }
    __syncthreads();

    // ---- Q fragments (persistent) ----
    unsigned qf[8][4];
    #pragma unroll
    for (int kc = 0; kc < 8; kc++) {
        qf[kc][0] = U(QP[(m0 + gID    ) * STR + kc * 8 + t4    ]);
        qf[kc][1] = U(QP[(m0 + gID + 8) * STR + kc * 8 + t4    ]);
        qf[kc][2] = U(QP[(m0 + gID    ) * STR + kc * 8 + t4 + 4]);
        qf[kc][3] = U(QP[(m0 + gID + 8) * STR + kc * 8 + t4 + 4]);
    }
    __syncwarp();   // all lanes' qf reads done before this warp's P writes

    float mA = -1e30f, mB = -1e30f, lA = 0.f, lB = 0.f;
    float oacc[4][2][4];   // [mc d-chunk][n0 q-half][frag]; O^T layout
    #pragma unroll
    for (int mc = 0; mc < 4; mc++)
        #pragma unroll
        for (int n0 = 0; n0 < 2; n0++)
            #pragma unroll
            for (int j = 0; j < 4; j++) oacc[mc][n0][j] = 0.f;

    const int ktiles = (seqlen + 63) >> 6;

    for (int kt = 0; kt < ktiles; kt++) {
        const float* Kc = Kb[kt & 1];
        const float* Vc = Vb[kt & 1];
        const bool havenext = (kt + 1 < ktiles);

        // ---- LDG next tile into registers (latency covered by S+softmax) ----
        float4 kst[4], vst[4];
        if (havenext) {
            int rg = (kt + 1) * 64 + lr;
            const float* bk = (rg < 128)
                ? (ek + ((b * 128  + rg            ) * 16 + h) * 64)
                : (gk + ((b * 1536 + soff + rg - 128) * 16 + h) * 64);
            const float* bv = (rg < 128)
                ? (ev + ((b * 128  + rg            ) * 16 + h) * 64)
                : (gv + ((b * 1536 + soff + rg - 128) * 16 + h) * 64);
            #pragma unroll
            for (int j = 0; j < 4; j++) {
                kst[j] = *(const float4*)(bk + (lq + 4 * j) * 4);
                vst[j] = *(const float4*)(bv + (lq + 4 * j) * 4);
            }
        }

        // ---- S = Q K^T (vectorized K-fragment loads) ----
        float sacc[8][4];
        #pragma unroll
        for (int nc = 0; nc < 8; nc++) {
            float kb0[8], kb1[8];
            const float* krow = Kc + (nc * 8 + gID) * STR;
            *(float4*)(kb0    ) = *(const float4*)(krow + t4 * 8);
            *(float4*)(kb0 + 4) = *(const float4*)(krow + t4 * 8 + 4);
            *(float4*)(kb1    ) = *(const float4*)(krow + (t4 + 4) * 8);
            *(float4*)(kb1 + 4) = *(const float4*)(krow + (t4 + 4) * 8 + 4);
            sacc[nc][0] = 0.f; sacc[nc][1] = 0.f; sacc[nc][2] = 0.f; sacc[nc][3] = 0.f;
            #pragma unroll
            for (int kc = 0; kc < 8; kc++)
                mma8(sacc[nc], qf[kc], U(kb0[kc]), U(kb1[kc]));
        }

        // ---- key-validity mask ----
        const int kbase = kt * 64;
        #pragma unroll
        for (int nc = 0; nc < 8; nc++) {
            int col0 = kbase + nc * 8 + 2 * t4;
            if (col0     >= seqlen) { sacc[nc][0] = -1e30f; sacc[nc][2] = -1e30f; }
            if (col0 + 1 >= seqlen) { sacc[nc][1] = -1e30f; sacc[nc][3] = -1e30f; }
        }

        // ---- online softmax (rows gID / gID+8; stats over 4 t4-lanes) ----
        float rmA = -1e30f, rmB = -1e30f;
        #pragma unroll
        for (int nc = 0; nc < 8; nc++) {
            rmA = fmaxf(rmA, fmaxf(sacc[nc][0], sacc[nc][1]));
            rmB = fmaxf(rmB, fmaxf(sacc[nc][2], sacc[nc][3]));
        }
        rmA = fmaxf(rmA, __shfl_xor_sync(0xffffffffu, rmA, 1));
        rmA = fmaxf(rmA, __shfl_xor_sync(0xffffffffu, rmA, 2));
        rmB = fmaxf(rmB, __shfl_xor_sync(0xffffffffu, rmB, 1));
        rmB = fmaxf(rmB, __shfl_xor_sync(0xffffffffu, rmB, 2));

        const float nmA = fmaxf(mA, rmA), nmB = fmaxf(mB, rmB);
        const float aA = ex2(mA - nmA), aB = ex2(mB - nmB);
        mA = nmA; mB = nmB;

        float sumA = 0.f, sumB = 0.f;
        #pragma unroll
        for (int nc = 0; nc < 8; nc++) {
            float p0 = ex2(sacc[nc][0] - nmA);
            float p1 = ex2(sacc[nc][1] - nmA);
            float p2 = ex2(sacc[nc][2] - nmB);
            float p3 = ex2(sacc[nc][3] - nmB);
            sumA += p0 + p1; sumB += p2 + p3;
            // permuted P store: pos(n) = (n&7)*8 + (n>>3); n = nc*8 + 2*t4 + j
            QP[(m0 + gID    ) * STR + (2 * t4    ) * 8 + nc] = __uint_as_float(f2tf(p0));
            QP[(m0 + gID    ) * STR + (2 * t4 + 1) * 8 + nc] = __uint_as_float(f2tf(p1));
            QP[(m0 + gID + 8) * STR + (2 * t4    ) * 8 + nc] = __uint_as_float(f2tf(p2));
            QP[(m0 + gID + 8) * STR + (2 * t4 + 1) * 8 + nc] = __uint_as_float(f2tf(p3));
        }
        sumA += __shfl_xor_sync(0xffffffffu, sumA, 1);
        sumA += __shfl_xor_sync(0xffffffffu, sumA, 2);
        sumB += __shfl_xor_sync(0xffffffffu, sumB, 1);
        sumB += __shfl_xor_sync(0xffffffffu, sumB, 2);
        lA = lA * aA + sumA;
        lB = lB * aB + sumB;

        // per-q-row alphas for the O^T layout (q-local = n0*8 + 2*t4 + j)
        const float alA0 = __shfl_sync(0xffffffffu, aA, (2 * t4    ) * 4);
        const float alA1 = __shfl_sync(0xffffffffu, aA, (2 * t4 + 1) * 4);
        const float alB0 = __shfl_sync(0xffffffffu, aB, (2 * t4    ) * 4);
        const float alB1 = __shfl_sync(0xffffffffu, aB, (2 * t4 + 1) * 4);
        #pragma unroll
        for (int mc = 0; mc < 4; mc++) {
            oacc[mc][0][0] *= alA0; oacc[mc][0][1] *= alA1;
            oacc[mc][0][2] *= alA0; oacc[mc][0][3] *= alA1;
            oacc[mc][1][0] *= alB0; oacc[mc][1][1] *= alB1;
            oacc[mc][1][2] *= alB0; oacc[mc][1][3] *= alB1;
        }

        // ---- STS next tile (target buffer idle since entry barrier) ----
        if (havenext) {
            float* Kn = Kb[(kt + 1) & 1];
            float* Vn = Vb[(kt + 1) & 1];
            const int pcol = ((lr & 7) << 3) + (lr >> 3);
            #pragma unroll
            for (int j = 0; j < 4; j++) {
                int d0 = (lq + 4 * j) * 4;
                float ka[4] = {kst[j].x, kst[j].y, kst[j].z, kst[j].w};
                float va[4] = {vst[j].x, vst[j].y, vst[j].z, vst[j].w};
                #pragma unroll
                for (int i = 0; i < 4; i++) {
                    int d = d0 + i;
                    Kn[lr * STR + ((d & 7) << 3) + (d >> 3)] = __uint_as_float(f2tf(ka[i]));
                    Vn[d * STR + pcol]                       = __uint_as_float(f2tf(va[i]));
                }
            }
        }
        __syncwarp();   // this warp's P writes visible to all its lanes

        // ---- O^T += V^T P^T (all loads vectorized) ----
        float pb0[2][8], pb1[2][8];
        #pragma unroll
        for (int n0 = 0; n0 < 2; n0++) {
            const float* pr = QP + (m0 + n0 * 8 + gID) * STR;
            *(float4*)(pb0[n0]    ) = *(const float4*)(pr + t4 * 8);
            *(float4*)(pb0[n0] + 4) = *(const float4*)(pr + t4 * 8 + 4);
            *(float4*)(pb1[n0]    ) = *(const float4*)(pr + (t4 + 4) * 8);
            *(float4*)(pb1[n0] + 4) = *(const float4*)(pr + (t4 + 4) * 8 + 4);
        }
        #pragma unroll
        for (int mc = 0; mc < 4; mc++) {
            float va0[8], va1[8], va2[8], va3[8];
            const float* v0 = Vc + (mc * 16 + gID    ) * STR;
            const float* v1 = Vc + (mc * 16 + gID + 8) * STR;
            *(float4*)(va0    ) = *(const float4*)(v0 + t4 * 8);
            *(float4*)(va0 + 4) = *(const float4*)(v0 + t4 * 8 + 4);
            *(float4*)(va2    ) = *(const float4*)(v0 + (t4 + 4) * 8);
            *(float4*)(va2 + 4) = *(const float4*)(v0 + (t4 + 4) * 8 + 4);
            *(float4*)(va1    ) = *(const float4*)(v1 + t4 * 8);
            *(float4*)(va1 + 4) = *(const float4*)(v1 + t4 * 8 + 4);
            *(float4*)(va3    ) = *(const float4*)(v1 + (t4 + 4) * 8);
            *(float4*)(va3 + 4) = *(const float4*)(v1 + (t4 + 4) * 8 + 4);
            #pragma unroll
            for (int n0 = 0; n0 < 2; n0++) {
                #pragma unroll
                for (int kc = 0; kc < 8; kc++) {
                    unsigned a[4] = {U(va0[kc]), U(va1[kc]), U(va2[kc]), U(va3[kc])};
                    mma8(oacc[mc][n0], a, U(pb0[n0][kc]), U(pb1[n0][kc]));
                }
            }
        }

        if (havenext) __syncthreads();
    }

    // ---- epilogue: normalize (per-q-row via shuffle) + packed store ----
    const float invA = 1.f / lA, invB = 1.f / lB;
    const float iA0 = __shfl_sync(0xffffffffu, invA, (2 * t4    ) * 4);
    const float iA1 = __shfl_sync(0xffffffffu, invA, (2 * t4 + 1) * 4);
    const float iB0 = __shfl_sync(0xffffffffu, invB, (2 * t4    ) * 4);
    const float iB1 = __shfl_sync(0xffffffffu, invB, (2 * t4 + 1) * 4);
    #pragma unroll
    for (int n0 = 0; n0 < 2; n0++) {
        const float s0 = n0 ? iB0 : iA0;
        const float s1 = n0 ? iB1 : iA1;
        const int qA = q0 + m0 + n0 * 8 + 2 * t4;
        #pragma unroll
        for (int mc = 0; mc < 4; mc++) {
            const int d = mc * 16 + gID;
            if (qA < seqlen) {
                float* dst = gout + (((long)(obase + qA)) * 16 + h) * 64 + d;
                dst[0] = oacc[mc][n0][0] * s0;
                dst[8] = oacc[mc][n0][2] * s0;
            }
            if (qA + 1 < seqlen) {
                float* dst = gout + (((long)(obase + qA + 1)) * 16 + h) * 64 + d;
                dst[0] = oacc[mc][n0][1] * s1;
                dst[8] = oacc[mc][n0][3] * s1;
            }
        }
    }
}

extern "C" void kernel_launch(void* const* d_in, const int* in_sizes, int n_in,
                              void* d_out, int out_size)
{
    const float* gq = (const float*)d_in[0];
    const float* gk = (const float*)d_in[1];
    const float* gv = (const float*)d_in[2];
    const float* eq = (const float*)d_in[3];
    const float* ek = (const float*)d_in[4];
    const float* ev = (const float*)d_in[5];
    float* out = (float*)d_out;

    const size_t smem_bytes = SM_TOTAL_FLOATS * sizeof(float);   // 104448 B
    cudaFuncSetAttribute(fa_tf32v_kernel,
                         cudaFuncAttributeMaxDynamicSharedMemorySize,
                         (int)smem_bytes);

    dim3 grid(48, 16, 1);   // 48 q-tiles (BQ=128) x 16 heads
    fa_tf32v_kernel<<<grid, NT, smem_bytes>>>(gq, gk, gv, eq, ek, ev, out);
}

// round 4
// speedup vs baseline: 1.5824x; 1.5824x over previous
#include <cuda_runtime.h>

// -----------------------------------------------------------------------------
// Round 4: R2 tf32 mma.sync flash attention + occupancy 8->12 warps/SM.
// BQ=64 x BK=64, D=64, 128 threads (4 warps, 16 q-rows each).
// Changes vs R2: P overlays Q smem (warp-private rows), V single-buffered
// (issued post-PV, consumed next PV), smem 106KB -> 70.7KB => 3 blocks/SM,
// __launch_bounds__(128,3).
// -----------------------------------------------------------------------------

#define NT 128
#define QKSCALE (0.125f * 1.44269504088896f)

// units sorted by descending seqlen for tail packing
__constant__ int c_seqlen[8] = {1152, 1008, 864, 720, 640, 560, 480, 400};
__constant__ int c_batch[8]  = {1,    5,    3,   7,   0,   4,   2,   6};
__constant__ int c_soff[8]   = {512,  512,  512, 512, 0,   0,   0,   0};
__constant__ int c_obase[8]  = {2080, 4096, 3232, 5104, 0, 1120, 640, 1680};
__constant__ int c_qstart[8] = {0, 18, 34, 48, 60, 70, 79, 87};   // cum ceil(seq/64); total 94

#define QS_STRIDE 68
#define KS_STRIDE 68
#define VS_STRIDE 72
// smem float offsets (Q/P overlaid)
#define SM_QP  0                                  // 64 x 68 (Q prologue, P mainloop)
#define SM_K0  (64*QS_STRIDE)                     // 4352
#define SM_K1  (SM_K0 + 64*KS_STRIDE)             // 8704
#define SM_V   (SM_K1 + 64*KS_STRIDE)             // 13056
#define SM_TOTAL_FLOATS (SM_V + 64*VS_STRIDE)     // 17664 floats = 70656 B

__device__ __forceinline__ unsigned f2tf(float f) {
    unsigned u; asm("cvt.rna.tf32.f32 %0, %1;" : "=r"(u) : "f"(f)); return u;
}
__device__ __forceinline__ float ex2(float x) {
    float y; asm("ex2.approx.f32 %0, %1;" : "=f"(y) : "f"(x)); return y;
}
__device__ __forceinline__ void mma8(float d[4], const unsigned a[4], unsigned b0, unsigned b1) {
    asm volatile("mma.sync.aligned.m16n8k8.row.col.f32.tf32.tf32.f32 "
                 "{%0,%1,%2,%3}, {%4,%5,%6,%7}, {%8,%9}, {%0,%1,%2,%3};"
                 : "+f"(d[0]), "+f"(d[1]), "+f"(d[2]), "+f"(d[3])
                 : "r"(a[0]), "r"(a[1]), "r"(a[2]), "r"(a[3]), "r"(b0), "r"(b1));
}
__device__ __forceinline__ void cpa16(float* s, const float* g) {
    unsigned sa = (unsigned)__cvta_generic_to_shared(s);
    asm volatile("cp.async.cg.shared.global [%0], [%1], 16;" :: "r"(sa), "l"(g));
}
#define CP_COMMIT() asm volatile("cp.async.commit_group;")
template <int N> __device__ __forceinline__ void cp_wait() {
    asm volatile("cp.async.wait_group %0;" :: "n"(N));
}
#define U(x) __float_as_uint(x)

__global__ __launch_bounds__(NT, 3) void fa_tf32_kernel(
    const float* __restrict__ gq, const float* __restrict__ gk, const float* __restrict__ gv,
    const float* __restrict__ eq, const float* __restrict__ ek, const float* __restrict__ ev,
    float* __restrict__ gout)
{
    extern __shared__ float sm[];
    float* QP = sm + SM_QP;                 // Q in prologue, P in mainloop
    float* Kb[2] = { sm + SM_K0, sm + SM_K1 };
    float* Vs = sm + SM_V;

    const int h  = blockIdx.y;
    const int bx = blockIdx.x;
    int u = 0;
    #pragma unroll
    for (int i = 1; i < 8; i++) u += (bx >= c_qstart[i]);
    const int seqlen = c_seqlen[u];
    const int q0     = (bx - c_qstart[u]) * 64;
    const int b      = c_batch[u];
    const int soff   = c_soff[u];
    const int obase  = c_obase[u];

    const int tid  = threadIdx.x;
    const int lane = tid & 31;
    const int gID  = lane >> 2;   // 0..7
    const int t4   = lane & 3;    // 0..3
    const int m0   = (tid >> 5) * 16;   // warp's local q-row base

    // ---- Q load: scale by 0.125*log2e, cvt to tf32, store to smem ----
    #pragma unroll
    for (int it = 0; it < 8; it++) {
        int idx = tid + NT * it;           // 0..1023 = 64 rows x 16 float4
        int row = idx >> 4, c4 = idx & 15;
        int rg  = q0 + row;                // < ceil64(seqlen) <= lc: valid memory
        const float* src = (rg < 128)
            ? (eq + (((b * 128  + rg            ) * 16 + h) * 64) + 4 * c4)
            : (gq + (((b * 1536 + soff + rg - 128) * 16 + h) * 64) + 4 * c4);
        float4 v = *(const float4*)src;
        uint4 o;
        o.x = f2tf(v.x * QKSCALE); o.y = f2tf(v.y * QKSCALE);
        o.z = f2tf(v.z * QKSCALE); o.w = f2tf(v.w * QKSCALE);
        *(uint4*)(QP + row * QS_STRIDE + 4 * c4) = o;
    }

    const int ktiles = (seqlen + 63) >> 6;

    // ---- prologue: issue K0 (group), V0 (group) ----
    #pragma unroll
    for (int it = 0; it < 8; it++) {
        int idx = tid + NT * it;
        int row = idx >> 4, c4 = idx & 15;
        int rg  = row;   // k0 = 0
        const float* sk = (rg < 128)
            ? (ek + (((b * 128  + rg            ) * 16 + h) * 64) + 4 * c4)
            : (gk + (((b * 1536 + soff + rg - 128) * 16 + h) * 64) + 4 * c4);
        cpa16(Kb[0] + row * KS_STRIDE + 4 * c4, sk);
    }
    CP_COMMIT();
    #pragma unroll
    for (int it = 0; it < 8; it++) {
        int idx = tid + NT * it;
        int row = idx >> 4, c4 = idx & 15;
        int rg  = row;
        const float* sv = (rg < 128)
            ? (ev + (((b * 128  + rg            ) * 16 + h) * 64) + 4 * c4)
            : (gv + (((b * 1536 + soff + rg - 128) * 16 + h) * 64) + 4 * c4);
        cpa16(Vs + row * VS_STRIDE + 4 * c4, sv);
    }
    CP_COMMIT();

    __syncthreads();   // Qs visible to all warps

    // ---- Q fragments (persistent) ----
    unsigned qf[8][4];
    #pragma unroll
    for (int kc = 0; kc < 8; kc++) {
        qf[kc][0] = U(QP[(m0 + gID    ) * QS_STRIDE + kc * 8 + t4    ]);
        qf[kc][1] = U(QP[(m0 + gID + 8) * QS_STRIDE + kc * 8 + t4    ]);
        qf[kc][2] = U(QP[(m0 + gID    ) * QS_STRIDE + kc * 8 + t4 + 4]);
        qf[kc][3] = U(QP[(m0 + gID + 8) * QS_STRIDE + kc * 8 + t4 + 4]);
    }
    __syncwarp();      // all lanes' Q reads done before this warp's P overwrites

    float mA = -1e30f, mB = -1e30f, lA = 0.f, lB = 0.f;
    float oacc[8][4];
    #pragma unroll
    for (int nc = 0; nc < 8; nc++)
        #pragma unroll
        for (int j = 0; j < 4; j++) oacc[nc][j] = 0.f;

    for (int kt = 0; kt < ktiles; kt++) {
        float* Kc = Kb[kt & 1];
        const bool havenext = (kt + 1 < ktiles);

        // issue next K tile into the other buffer (its contents were consumed
        // in iter kt-1; bottom-of-iter barrier protected the overwrite)
        if (havenext) {
            const int k0n = (kt + 1) * 64;
            float* Kn = Kb[(kt + 1) & 1];
            #pragma unroll
            for (int it = 0; it < 8; it++) {
                int idx = tid + NT * it;
                int row = idx >> 4, c4 = idx & 15;
                int rg  = k0n + row;
                const float* sk = (rg < 128)
                    ? (ek + (((b * 128  + rg            ) * 16 + h) * 64) + 4 * c4)
                    : (gk + (((b * 1536 + soff + rg - 128) * 16 + h) * 64) + 4 * c4);
                cpa16(Kn + row * KS_STRIDE + 4 * c4, sk);
            }
            CP_COMMIT();
            cp_wait<1>();   // K(kt) and V(kt) groups complete; K(kt+1) may fly
        } else {
            cp_wait<0>();
        }
        __syncthreads();

        // ---- S = Q K^T : 8 n-chunks x 8 k-chunks of m16n8k8 ----
        float sacc[8][4];
        #pragma unroll
        for (int nc = 0; nc < 8; nc++) {
            sacc[nc][0] = 0.f; sacc[nc][1] = 0.f; sacc[nc][2] = 0.f; sacc[nc][3] = 0.f;
            #pragma unroll
            for (int kc = 0; kc < 8; kc++) {
                unsigned b0 = U(Kc[(nc * 8 + gID) * KS_STRIDE + kc * 8 + t4    ]);
                unsigned b1 = U(Kc[(nc * 8 + gID) * KS_STRIDE + kc * 8 + t4 + 4]);
                mma8(sacc[nc], qf[kc], b0, b1);
            }
        }

        // ---- key-validity mask ----
        const int kbase = kt * 64;
        #pragma unroll
        for (int nc = 0; nc < 8; nc++) {
            int col0 = kbase + nc * 8 + 2 * t4;
            if (col0     >= seqlen) { sacc[nc][0] = -1e30f; sacc[nc][2] = -1e30f; }
            if (col0 + 1 >= seqlen) { sacc[nc][1] = -1e30f; sacc[nc][3] = -1e30f; }
        }

        // ---- online softmax (rows gID / gID+8; stats over 4 t4-lanes) ----
        float rmA = -1e30f, rmB = -1e30f;
        #pragma unroll
        for (int nc = 0; nc < 8; nc++) {
            rmA = fmaxf(rmA, fmaxf(sacc[nc][0], sacc[nc][1]));
            rmB = fmaxf(rmB, fmaxf(sacc[nc][2], sacc[nc][3]));
        }
        rmA = fmaxf(rmA, __shfl_xor_sync(0xffffffffu, rmA, 1));
        rmA = fmaxf(rmA, __shfl_xor_sync(0xffffffffu, rmA, 2));
        rmB = fmaxf(rmB, __shfl_xor_sync(0xffffffffu, rmB, 1));
        rmB = fmaxf(rmB, __shfl_xor_sync(0xffffffffu, rmB, 2));

        const float nmA = fmaxf(mA, rmA), nmB = fmaxf(mB, rmB);
        const float aA = ex2(mA - nmA), aB = ex2(mB - nmB);
        mA = nmA; mB = nmB;

        float sumA = 0.f, sumB = 0.f;
        #pragma unroll
        for (int nc = 0; nc < 8; nc++) {
            float p0 = ex2(sacc[nc][0] - nmA);
            float p1 = ex2(sacc[nc][1] - nmA);
            float p2 = ex2(sacc[nc][2] - nmB);
            float p3 = ex2(sacc[nc][3] - nmB);
            sumA += p0 + p1; sumB += p2 + p3;
            uint2 wA; wA.x = f2tf(p0); wA.y = f2tf(p1);
            uint2 wB; wB.x = f2tf(p2); wB.y = f2tf(p3);
            *(uint2*)(QP + (m0 + gID    ) * QS_STRIDE + nc * 8 + 2 * t4) = wA;
            *(uint2*)(QP + (m0 + gID + 8) * QS_STRIDE + nc * 8 + 2 * t4) = wB;
        }
        sumA += __shfl_xor_sync(0xffffffffu, sumA, 1);
        sumA += __shfl_xor_sync(0xffffffffu, sumA, 2);
        sumB += __shfl_xor_sync(0xffffffffu, sumB, 1);
        sumB += __shfl_xor_sync(0xffffffffu, sumB, 2);
        lA = lA * aA + sumA;
        lB = lB * aB + sumB;

        #pragma unroll
        for (int nc = 0; nc < 8; nc++) {
            oacc[nc][0] *= aA; oacc[nc][1] *= aA;
            oacc[nc][2] *= aB; oacc[nc][3] *= aB;
        }
        __syncwarp();   // warp-private P rows written before reads

        // ---- O += P V : k over keys (8 chunks), n over d (8 chunks) ----
        #pragma unroll
        for (int kc = 0; kc < 8; kc++) {
            unsigned a[4];
            a[0] = U(QP[(m0 + gID    ) * QS_STRIDE + kc * 8 + t4    ]);
            a[1] = U(QP[(m0 + gID + 8) * QS_STRIDE + kc * 8 + t4    ]);
            a[2] = U(QP[(m0 + gID    ) * QS_STRIDE + kc * 8 + t4 + 4]);
            a[3] = U(QP[(m0 + gID + 8) * QS_STRIDE + kc * 8 + t4 + 4]);
            #pragma unroll
            for (int nc = 0; nc < 8; nc++) {
                unsigned b0 = U(Vs[(kc * 8 + t4    ) * VS_STRIDE + nc * 8 + gID]);
                unsigned b1 = U(Vs[(kc * 8 + t4 + 4) * VS_STRIDE + nc * 8 + gID]);
                mma8(oacc[nc], a, b0, b1);
            }
        }

        // all warps done reading Vs (and this tile's P) before V(kt+1) lands
        __syncthreads();

        // ---- issue V(kt+1) into the (now idle) single V buffer ----
        if (havenext) {
            const int k0n = (kt + 1) * 64;
            #pragma unroll
            for (int it = 0; it < 8; it++) {
                int idx = tid + NT * it;
                int row = idx >> 4, c4 = idx & 15;
                int rg  = k0n + row;
                const float* sv = (rg < 128)
                    ? (ev + (((b * 128  + rg            ) * 16 + h) * 64) + 4 * c4)
                    : (gv + (((b * 1536 + soff + rg - 128) * 16 + h) * 64) + 4 * c4);
                cpa16(Vs + row * VS_STRIDE + 4 * c4, sv);
            }
            CP_COMMIT();
        }
    }

    // ---- epilogue: normalize + packed store ----
    const float invA = 1.f / lA, invB = 1.f / lB;
    const int qrA = q0 + m0 + gID;
    const int qrB = qrA + 8;
    #pragma unroll
    for (int nc = 0; nc < 8; nc++) {
        const int col = nc * 8 + 2 * t4;
        if (qrA < seqlen) {
            float2 v; v.x = oacc[nc][0] * invA; v.y = oacc[nc][1] * invA;
            *(float2*)(gout + (((long)(obase + qrA)) * 16 + h) * 64 + col) = v;
        }
        if (qrB < seqlen) {
            float2 v; v.x = oacc[nc][2] * invB; v.y = oacc[nc][3] * invB;
            *(float2*)(gout + (((long)(obase + qrB)) * 16 + h) * 64 + col) = v;
        }
    }
}

extern "C" void kernel_launch(void* const* d_in, const int* in_sizes, int n_in,
                              void* d_out, int out_size)
{
    const float* gq = (const float*)d_in[0];
    const float* gk = (const float*)d_in[1];
    const float* gv = (const float*)d_in[2];
    const float* eq = (const float*)d_in[3];
    const float* ek = (const float*)d_in[4];
    const float* ev = (const float*)d_in[5];
    float* out = (float*)d_out;

    const size_t smem_bytes = SM_TOTAL_FLOATS * sizeof(float);   // 70656 B
    cudaFuncSetAttribute(fa_tf32_kernel,
                         cudaFuncAttributeMaxDynamicSharedMemorySize,
                         (int)smem_bytes);

    dim3 grid(94, 16, 1);   // 94 q-tiles (BQ=64) x 16 heads
    fa_tf32_kernel<<<grid, NT, smem_bytes>>>(gq, gk, gv, eq, ek, ev, out);
}